// round 7
// baseline (speedup 1.0000x reference)
#include <cuda_runtime.h>
#include <cuda_bf16.h>
#include <cstdint>

#define S 4096
#define GRID 128
#define BLOCK 544          // 16 compute warps + 1 poller warp
#define RPB 32             // rows per block
#define RPG 8              // rows per warp
#define KQ 1024            // K quarter
#define ROWSTRIDE (S / 8)  // uint4 per row

// ---------------- device-global scratch ----------------
static __device__ __nv_bfloat16 g_M[(size_t)S * S];     // exp(log_trans), bf16
static __device__ float g_w[2][S];                      // ping-pong unnormalized filter
static __device__ unsigned long long g_flag[2][GRID];   // {f32 partialZ:hi, u32 gen:lo}

// ---------------- prep: M = bf16(exp(log_trans)) (EXACT, no debias) ----------------
__global__ void hmm_prep_kernel(const float* __restrict__ log_trans) {
    size_t gtid = (size_t)blockIdx.x * blockDim.x + threadIdx.x;
    if (gtid < 2 * GRID) g_flag[gtid / GRID][gtid % GRID] = 0ull;
    const size_t n4 = (size_t)S * S / 4;
    const size_t stride = (size_t)gridDim.x * blockDim.x;
    for (size_t i = gtid; i < n4; i += stride) {
        float4 v = reinterpret_cast<const float4*>(log_trans)[i];
        __nv_bfloat162 lo, hi;
        lo.x = __float2bfloat16(__expf(v.x));
        lo.y = __float2bfloat16(__expf(v.y));
        hi.x = __float2bfloat16(__expf(v.z));
        hi.y = __float2bfloat16(__expf(v.w));
        reinterpret_cast<__nv_bfloat162*>(g_M)[2 * i]     = lo;
        reinterpret_cast<__nv_bfloat162*>(g_M)[2 * i + 1] = hi;
    }
}

// ---------------- helpers ----------------
__device__ __forceinline__ float warp_sum(float v) {
#pragma unroll
    for (int o = 16; o; o >>= 1) v += __shfl_xor_sync(0xffffffffu, v, o);
    return v;
}

// EXACT bf16 pair -> f32x2 (2 ALU ops; the 1-op version was biased)
__device__ __forceinline__ unsigned long long cvt2(unsigned u) {
    unsigned long long r;
    asm("mov.b64 %0, {%1, %2};" : "=l"(r) : "r"(u << 16), "r"(u & 0xffff0000u));
    return r;
}

__device__ __forceinline__ unsigned long long fma2(unsigned long long a,
                                                   unsigned long long b,
                                                   unsigned long long c) {
    unsigned long long d;
    asm("fma.rn.f32x2 %0, %1, %2, %3;" : "=l"(d) : "l"(a), "l"(b), "l"(c));
    return d;
}

__device__ __forceinline__ float f32x2_hsum(unsigned long long v) {
    unsigned lo, hi;
    asm("mov.b64 {%0, %1}, %2;" : "=r"(lo), "=r"(hi) : "l"(v));
    return __uint_as_float(lo) + __uint_as_float(hi);
}

__device__ __forceinline__ unsigned long long ldacq(const unsigned long long* p) {
    unsigned long long v;
    asm volatile("ld.acquire.gpu.global.b64 %0, [%1];" : "=l"(v) : "l"(p) : "memory");
    return v;
}
__device__ __forceinline__ void strel(unsigned long long* p, unsigned long long v) {
    asm volatile("st.release.gpu.global.b64 [%0], %1;" :: "l"(p), "l"(v) : "memory");
}
__device__ __forceinline__ void strelax(float* p, float v) {
    asm volatile("st.relaxed.gpu.global.f32 [%0], %1;" :: "l"(p), "f"(v) : "memory");
}

__device__ __forceinline__ unsigned smem_u32(const void* p) {
    return (unsigned)__cvta_generic_to_shared(p);
}

__device__ __forceinline__ void mbar_wait(unsigned mb, unsigned ph) {
    asm volatile(
        "{\n\t"
        ".reg .pred P;\n\t"
        "W%=:\n\t"
        "mbarrier.try_wait.parity.acquire.cta.shared::cta.b64 P, [%0], %1, 0x989680;\n\t"
        "@!P bra W%=;\n\t"
        "}"
        :: "r"(mb), "r"(ph) : "memory");
}

// final-Z poll (warp collective, bid0 warp0 only)
__device__ __forceinline__ float poll_all(unsigned gen, int lane) {
    const unsigned long long* base = g_flag[gen & 1];
    unsigned long long x0, x1, x2, x3;
    for (;;) {
        x0 = ldacq(base + lane);
        x1 = ldacq(base + lane + 32);
        x2 = ldacq(base + lane + 64);
        x3 = ldacq(base + lane + 96);
        if (((unsigned)x0 == gen) & ((unsigned)x1 == gen) &
            ((unsigned)x2 == gen) & ((unsigned)x3 == gen)) break;
    }
    float z = __uint_as_float((unsigned)(x0 >> 32)) +
              __uint_as_float((unsigned)(x1 >> 32)) +
              __uint_as_float((unsigned)(x2 >> 32)) +
              __uint_as_float((unsigned)(x3 >> 32));
    return warp_sum(z);
}

// ---------------- persistent forward-filter kernel ----------------
__global__ void __launch_bounds__(BLOCK, 1) hmm_main_kernel(
    const float* __restrict__ log_M0,
    const float* __restrict__ log_emit,
    const int*   __restrict__ Tptr,
    float*       __restrict__ out)
{
    __shared__ __align__(128) float sw[2][S];           // double-buffered w (TMA dst)
    __shared__ __align__(16) float s_red[RPB][4];
    __shared__ float s_Z[2];
    __shared__ volatile int s_zgen;
    __shared__ __align__(8) unsigned long long s_mbar[4];

    const int tid  = threadIdx.x;
    const int lane = tid & 31;
    const int warp = tid >> 5;
    const int bid  = blockIdx.x;
    const int T    = *Tptr;

    const unsigned sw_base = smem_u32(sw);
    const unsigned mb_base = smem_u32(s_mbar);

    if (tid == 0) {
        s_zgen = 0;
#pragma unroll
        for (int qq = 0; qq < 4; ++qq)
            asm volatile("mbarrier.init.shared.b64 [%0], 1;"
                         :: "r"(mb_base + 8 * qq) : "memory");
    }
    __syncthreads();

    const int r0 = bid * RPB;
    double lik = 0.0;

    // ---- t = 0: w0 = exp(log_M0 + log_emit[0]); publish gen 1 ----
    if (warp == 0) {
        int row = r0 + lane;
        float v = __expf(__ldcg(log_M0 + row) + __ldcg(log_emit + row));
        strelax(&g_w[0][row], v);
        float part = warp_sum(v);
        __syncwarp();
        if (lane == 0)
            strel(&g_flag[1][bid],
                  ((unsigned long long)__float_as_uint(part) << 32) | 1u);
    }

    if (warp == 16) {
        // ================= POLLER WARP =================
        for (int t = 1; t <= T; ++t) {
            const unsigned gen = (unsigned)t;
            const unsigned long long* base = g_flag[t & 1];
            const float* src = g_w[(t - 1) & 1];
            const unsigned dstb = sw_base + (unsigned)(t & 1) * (S * 4);
            unsigned issued = 0;
            float zacc = 0.f;
            while (issued != 0xFu) {
                unsigned long long x0 = ldacq(base + lane);
                unsigned long long x1 = ldacq(base + lane + 32);
                unsigned long long x2 = ldacq(base + lane + 64);
                unsigned long long x3 = ldacq(base + lane + 96);
                unsigned long long xs[4] = {x0, x1, x2, x3};
#pragma unroll
                for (int qq = 0; qq < 4; ++qq) {
                    if (!(issued & (1u << qq)) &&
                        __all_sync(0xffffffffu, (unsigned)xs[qq] == gen)) {
                        zacc += warp_sum(__uint_as_float((unsigned)(xs[qq] >> 32)));
                        issued |= 1u << qq;
                        if (lane == 0) {
                            unsigned mb = mb_base + 8 * qq;
                            asm volatile("mbarrier.arrive.expect_tx.shared.b64 _, [%0], %1;"
                                         :: "r"(mb), "r"(4096u) : "memory");
                            asm volatile("fence.proxy.async;" ::: "memory");
                            asm volatile(
                                "cp.async.bulk.shared::cta.global.mbarrier::complete_tx::bytes "
                                "[%0], [%1], %2, [%3];"
                                :: "r"(dstb + qq * 4096u), "l"(src + qq * KQ),
                                   "r"(4096u), "r"(mb) : "memory");
                        }
                    }
                }
            }
            if (lane == 0) {
                s_Z[t & 1] = zacc;
                __threadfence_block();
                s_zgen = t;
            }
        }
    } else {
        // ================= 16 COMPUTE WARPS =================
        const int g = warp >> 2;   // row group 0..3
        const int q = warp & 3;    // K quarter 0..3
        const uint4* A = reinterpret_cast<const uint4*>(
            g_M + (size_t)(r0 + g * RPG) * S + q * KQ);
        const unsigned my_mb = mb_base + 8 * q;

        for (int t = 1; t <= T; ++t) {
            const int buf = t & 1;
            const unsigned ph = (unsigned)((t - 1) & 1);
            const float* swq = sw[buf] + q * KQ;

            float em = 0.f;
            if (warp == 0) em = __ldcg(log_emit + (size_t)t * S + r0 + lane);

            // prefetch streamed rows (6,7) — latency hides under the mbar sleep
            uint4 pf[8];
#pragma unroll
            for (int c = 0; c < 4; ++c) {
                float4 t6 = __ldcg(reinterpret_cast<const float4*>(A) + 6 * ROWSTRIDE + c * 32 + lane);
                float4 t7 = __ldcg(reinterpret_cast<const float4*>(A) + 7 * ROWSTRIDE + c * 32 + lane);
                pf[c]     = *reinterpret_cast<uint4*>(&t6);
                pf[4 + c] = *reinterpret_cast<uint4*>(&t7);
            }

            mbar_wait(my_mb, ph);   // quarter q of w_{t-1} is in sw[buf]

            unsigned long long acc[8] = {0ull, 0ull, 0ull, 0ull, 0ull, 0ull, 0ull, 0ull};
#pragma unroll
            for (int c = 0; c < 4; ++c) {
                const int kb = c * 32 + lane;
                const ulonglong2 w01 = *reinterpret_cast<const ulonglong2*>(swq + c * 256 + lane * 8);
                const ulonglong2 w23 = *reinterpret_cast<const ulonglong2*>(swq + c * 256 + lane * 8 + 4);
#pragma unroll
                for (int r = 0; r < 6; ++r) {
                    uint4 a = A[r * ROWSTRIDE + kb];     // L1-pinned
                    acc[r] = fma2(cvt2(a.x), w01.x, acc[r]);
                    acc[r] = fma2(cvt2(a.y), w01.y, acc[r]);
                    acc[r] = fma2(cvt2(a.z), w23.x, acc[r]);
                    acc[r] = fma2(cvt2(a.w), w23.y, acc[r]);
                }
                {
                    uint4 a = pf[c];
                    acc[6] = fma2(cvt2(a.x), w01.x, acc[6]);
                    acc[6] = fma2(cvt2(a.y), w01.y, acc[6]);
                    acc[6] = fma2(cvt2(a.z), w23.x, acc[6]);
                    acc[6] = fma2(cvt2(a.w), w23.y, acc[6]);
                    uint4 b = pf[4 + c];
                    acc[7] = fma2(cvt2(b.x), w01.x, acc[7]);
                    acc[7] = fma2(cvt2(b.y), w01.y, acc[7]);
                    acc[7] = fma2(cvt2(b.z), w23.x, acc[7]);
                    acc[7] = fma2(cvt2(b.w), w23.y, acc[7]);
                }
            }

#pragma unroll
            for (int r = 0; r < 8; ++r) {
                float s = warp_sum(f32x2_hsum(acc[r]));
                if (lane == 0) s_red[g * RPG + r][q] = s;
            }
            asm volatile("bar.sync 1, 512;" ::: "memory");   // compute warps only

            if (warp == 0) {
                while (s_zgen < t) { }                       // poller handoff (smem)
                float Z = s_Z[t & 1];
                float invZ = 1.0f / Z;
                if (bid == 0 && lane == 0) lik += (double)logf(Z);
                float4 p = *reinterpret_cast<const float4*>(s_red[lane]);
                float dotv = (p.x + p.y) + (p.z + p.w);
                float v = dotv * __expf(em) * invZ;
                strelax(&g_w[buf][r0 + lane], v);
                float part = warp_sum(v);
                __syncwarp();
                const unsigned gen_out = (unsigned)(t + 1);
                if (lane == 0)
                    strel(&g_flag[gen_out & 1][bid],
                          ((unsigned long long)__float_as_uint(part) << 32) | gen_out);
            }
        }

        // final Z_T
        if (bid == 0 && warp == 0) {
            float Z = poll_all((unsigned)(T + 1), lane);
            if (lane == 0) {
                lik += (double)logf(Z);
                out[0] = (float)lik;
            }
        }
    }
}

// ---------------- launch ----------------
extern "C" void kernel_launch(void* const* d_in, const int* in_sizes, int n_in,
                              void* d_out, int out_size) {
    const float* log_M0    = (const float*)d_in[0];
    const float* log_trans = (const float*)d_in[1];
    const float* log_emit  = (const float*)d_in[2];
    const int*   Tptr      = (const int*)d_in[3];
    float* out = (float*)d_out;

    hmm_prep_kernel<<<2048, 256>>>(log_trans);
    hmm_main_kernel<<<GRID, BLOCK>>>(log_M0, log_emit, Tptr, out);
}

// round 8
// speedup vs baseline: 1.1668x; 1.1668x over previous
#include <cuda_runtime.h>
#include <cuda_bf16.h>
#include <cstdint>

#define S 4096
#define GRID 128
#define BLOCK 512
#define RPB 32             // rows per block
#define RPG 8              // rows per warp
#define KQ 1024            // K quarter per warp
#define ROWSTRIDE (S / 8)  // uint4 per row

// ---------------- device-global scratch ----------------
static __device__ __nv_bfloat16 g_M[(size_t)S * S];     // exp(log_trans), bf16
static __device__ float g_w[2][S];                      // ping-pong unnormalized filter
static __device__ unsigned long long g_flag[2][GRID];   // {f32 partialZ:hi, u32 gen:lo}

// ---------------- prep: M = bf16(exp(log_trans)); reset flags ----------------
__global__ void hmm_prep_kernel(const float* __restrict__ log_trans) {
    size_t gtid = (size_t)blockIdx.x * blockDim.x + threadIdx.x;
    if (gtid < 2 * GRID) g_flag[gtid / GRID][gtid % GRID] = 0ull;
    const size_t n4 = (size_t)S * S / 4;
    const size_t stride = (size_t)gridDim.x * blockDim.x;
    for (size_t i = gtid; i < n4; i += stride) {
        float4 v = reinterpret_cast<const float4*>(log_trans)[i];
        __nv_bfloat162 lo, hi;
        lo.x = __float2bfloat16(__expf(v.x));
        lo.y = __float2bfloat16(__expf(v.y));
        hi.x = __float2bfloat16(__expf(v.z));
        hi.y = __float2bfloat16(__expf(v.w));
        reinterpret_cast<__nv_bfloat162*>(g_M)[2 * i]     = lo;
        reinterpret_cast<__nv_bfloat162*>(g_M)[2 * i + 1] = hi;
    }
}

// ---------------- helpers ----------------
__device__ __forceinline__ float warp_sum(float v) {
#pragma unroll
    for (int o = 16; o; o >>= 1) v += __shfl_xor_sync(0xffffffffu, v, o);
    return v;
}

// EXACT bf16 pair -> f32x2
__device__ __forceinline__ unsigned long long cvt2(unsigned u) {
    unsigned long long r;
    asm("mov.b64 %0, {%1, %2};" : "=l"(r) : "r"(u << 16), "r"(u & 0xffff0000u));
    return r;
}

__device__ __forceinline__ unsigned long long fma2(unsigned long long a,
                                                   unsigned long long b,
                                                   unsigned long long c) {
    unsigned long long d;
    asm("fma.rn.f32x2 %0, %1, %2, %3;" : "=l"(d) : "l"(a), "l"(b), "l"(c));
    return d;
}

__device__ __forceinline__ float f32x2_hsum(unsigned long long v) {
    unsigned lo, hi;
    asm("mov.b64 {%0, %1}, %2;" : "=r"(lo), "=r"(hi) : "l"(v));
    return __uint_as_float(lo) + __uint_as_float(hi);
}

__device__ __forceinline__ unsigned long long ldacq(const unsigned long long* p) {
    unsigned long long v;
    asm volatile("ld.acquire.gpu.global.b64 %0, [%1];" : "=l"(v) : "l"(p) : "memory");
    return v;
}
__device__ __forceinline__ void strel(unsigned long long* p, unsigned long long v) {
    asm volatile("st.release.gpu.global.b64 [%0], %1;" :: "l"(p), "l"(v) : "memory");
}
__device__ __forceinline__ void strelax(float* p, float v) {
    asm volatile("st.relaxed.gpu.global.f32 [%0], %1;" :: "l"(p), "f"(v) : "memory");
}

// 16B L2-direct load (w chunks)
__device__ __forceinline__ ulonglong2 ldcg2(const float* p) {
    ulonglong2 v;
    asm volatile("ld.global.cg.v2.u64 {%0, %1}, [%2];"
                 : "=l"(v.x), "=l"(v.y) : "l"(p));
    return v;
}

// Barrier + Z-reduce: WARP 0 ONLY, short post-publish window (R4-proven).
// nanosleep backoff caps poll pressure on the 8 flag lines so the flag
// WRITES (the critical path) aren't queued behind poll reads.
__device__ __forceinline__ float poll_all(unsigned gen, int lane) {
    const unsigned long long* base = g_flag[gen & 1];
    unsigned long long x0, x1, x2, x3;
    for (;;) {
        x0 = ldacq(base + lane);
        x1 = ldacq(base + lane + 32);
        x2 = ldacq(base + lane + 64);
        x3 = ldacq(base + lane + 96);
        if (((unsigned)x0 == gen) & ((unsigned)x1 == gen) &
            ((unsigned)x2 == gen) & ((unsigned)x3 == gen)) break;
        __nanosleep(40);
    }
    float z = __uint_as_float((unsigned)(x0 >> 32)) +
              __uint_as_float((unsigned)(x1 >> 32)) +
              __uint_as_float((unsigned)(x2 >> 32)) +
              __uint_as_float((unsigned)(x3 >> 32));
    return warp_sum(z);
}

// ---------------- persistent forward-filter kernel ----------------
__global__ void __launch_bounds__(BLOCK, 1) hmm_main_kernel(
    const float* __restrict__ log_M0,
    const float* __restrict__ log_emit,
    const int*   __restrict__ Tptr,
    float*       __restrict__ out)
{
    __shared__ __align__(16) float s_red[RPB][4];

    const int tid  = threadIdx.x;
    const int lane = tid & 31;
    const int warp = tid >> 5;
    const int g    = warp >> 2;   // row group 0..3
    const int q    = warp & 3;    // K quarter 0..3
    const int bid  = blockIdx.x;
    const int T    = *Tptr;

    const int r0 = bid * RPB;
    const uint4* A = reinterpret_cast<const uint4*>(
        g_M + (size_t)(r0 + g * RPG) * S + q * KQ);

    double lik = 0.0;
    float invZ = 0.f;

    // ---- t = 0 ----
    if (warp == 0) {
        int row = r0 + lane;
        float v = __expf(__ldcg(log_M0 + row) + __ldcg(log_emit + row));
        strelax(&g_w[0][row], v);
        float part = warp_sum(v);
        __syncwarp();
        if (lane == 0)
            strel(&g_flag[1][bid],
                  ((unsigned long long)__float_as_uint(part) << 32) | 1u);
        float Z = poll_all(1u, lane);
        invZ = 1.0f / Z;
        if (bid == 0 && tid == 0) lik += (double)logf(Z);
    }

    // prefetch streamed rows (6,7) for step 1 — addresses are t-invariant
    uint4 pf[8];
#pragma unroll
    for (int c = 0; c < 4; ++c) {
        float4 t6 = __ldcg(reinterpret_cast<const float4*>(A) + 6 * ROWSTRIDE + c * 32 + lane);
        float4 t7 = __ldcg(reinterpret_cast<const float4*>(A) + 7 * ROWSTRIDE + c * 32 + lane);
        pf[c]     = *reinterpret_cast<uint4*>(&t6);
        pf[4 + c] = *reinterpret_cast<uint4*>(&t7);
    }
    __syncthreads();   // others wait for warp 0's poll (w0 globally visible)

    for (int t = 1; t <= T; ++t) {
        const int cur = t & 1, prev = cur ^ 1;
        const unsigned gen = (unsigned)(t + 1);

        // emit prefetch (warp 0 only; consumed in epilogue)
        float em = 0.f;
        if (warp == 0) em = __ldcg(log_emit + (size_t)t * S + r0 + lane);

        // per-lane w chunks straight from L2 — no smem staging, no extra sync.
        // Safe: the trailing barrier of step t-1 is ordered after warp 0's
        // poll(gen t), which certifies all of w_{t-1} is globally visible.
        const float* wsrc = g_w[prev] + q * KQ + lane * 8;
        ulonglong2 wv[8];
#pragma unroll
        for (int c = 0; c < 4; ++c) {
            wv[2 * c]     = ldcg2(wsrc + c * 256);
            wv[2 * c + 1] = ldcg2(wsrc + c * 256 + 4);
        }

        unsigned long long acc[8] = {0ull, 0ull, 0ull, 0ull, 0ull, 0ull, 0ull, 0ull};
#pragma unroll
        for (int c = 0; c < 4; ++c) {
            const int kb = c * 32 + lane;
            const ulonglong2 w01 = wv[2 * c];
            const ulonglong2 w23 = wv[2 * c + 1];
#pragma unroll
            for (int r = 0; r < 6; ++r) {
                uint4 a = A[r * ROWSTRIDE + kb];     // L1-pinned rows
                acc[r] = fma2(cvt2(a.x), w01.x, acc[r]);
                acc[r] = fma2(cvt2(a.y), w01.y, acc[r]);
                acc[r] = fma2(cvt2(a.z), w23.x, acc[r]);
                acc[r] = fma2(cvt2(a.w), w23.y, acc[r]);
            }
            {
                uint4 a = pf[c];
                acc[6] = fma2(cvt2(a.x), w01.x, acc[6]);
                acc[6] = fma2(cvt2(a.y), w01.y, acc[6]);
                acc[6] = fma2(cvt2(a.z), w23.x, acc[6]);
                acc[6] = fma2(cvt2(a.w), w23.y, acc[6]);
                uint4 b = pf[4 + c];
                acc[7] = fma2(cvt2(b.x), w01.x, acc[7]);
                acc[7] = fma2(cvt2(b.y), w01.y, acc[7]);
                acc[7] = fma2(cvt2(b.z), w23.x, acc[7]);
                acc[7] = fma2(cvt2(b.w), w23.y, acc[7]);
            }
        }

#pragma unroll
        for (int r = 0; r < 8; ++r) {
            float s = warp_sum(f32x2_hsum(acc[r]));
            if (lane == 0) s_red[g * RPG + r][q] = s;
        }
        __syncthreads();

        // refill streamed-row prefetch for t+1 NOW — latency hides under
        // warp 0's epilogue + poll below
#pragma unroll
        for (int c = 0; c < 4; ++c) {
            float4 t6 = __ldcg(reinterpret_cast<const float4*>(A) + 6 * ROWSTRIDE + c * 32 + lane);
            float4 t7 = __ldcg(reinterpret_cast<const float4*>(A) + 7 * ROWSTRIDE + c * 32 + lane);
            pf[c]     = *reinterpret_cast<uint4*>(&t6);
            pf[4 + c] = *reinterpret_cast<uint4*>(&t7);
        }

        // epilogue + publish + barrier: warp 0 only; others park at bar.sync
        if (warp == 0) {
            float4 p = *reinterpret_cast<const float4*>(s_red[lane]);
            float dotv = (p.x + p.y) + (p.z + p.w);
            float v = dotv * __expf(em) * invZ;
            strelax(&g_w[cur][r0 + lane], v);
            float part = warp_sum(v);
            __syncwarp();
            if (lane == 0)
                strel(&g_flag[gen & 1][bid],
                      ((unsigned long long)__float_as_uint(part) << 32) | gen);
            float Z = poll_all(gen, lane);
            invZ = 1.0f / Z;
            if (bid == 0 && tid == 0) lik += (double)logf(Z);
        }
        __syncthreads();
    }

    if (bid == 0 && tid == 0) out[0] = (float)lik;
}

// ---------------- launch ----------------
extern "C" void kernel_launch(void* const* d_in, const int* in_sizes, int n_in,
                              void* d_out, int out_size) {
    const float* log_M0    = (const float*)d_in[0];
    const float* log_trans = (const float*)d_in[1];
    const float* log_emit  = (const float*)d_in[2];
    const int*   Tptr      = (const int*)d_in[3];
    float* out = (float*)d_out;

    hmm_prep_kernel<<<2048, 256>>>(log_trans);
    hmm_main_kernel<<<GRID, BLOCK>>>(log_M0, log_emit, Tptr, out);
}

// round 9
// speedup vs baseline: 1.4963x; 1.2824x over previous
#include <cuda_runtime.h>
#include <cuda_bf16.h>
#include <cstdint>

#define S 4096
#define GRID 128
#define BLOCK 512
#define NWARP 16
#define RPB 32             // rows per block
#define RPG 8              // rows per warp
#define KQ 1024            // K quarter per warp
#define ROWSTRIDE (S / 8)  // uint4 per row

// ---------------- device-global scratch ----------------
static __device__ __nv_bfloat16 g_M[(size_t)S * S];     // exp(log_trans), bf16
static __device__ float g_w[2][S];                      // ping-pong unnormalized filter
static __device__ unsigned long long g_flag[2][GRID];   // {f32 partialZ:hi, u32 gen:lo}

// ---------------- prep: M = bf16(exp(log_trans)); reset flags ----------------
__global__ void hmm_prep_kernel(const float* __restrict__ log_trans) {
    size_t gtid = (size_t)blockIdx.x * blockDim.x + threadIdx.x;
    if (gtid < 2 * GRID) g_flag[gtid / GRID][gtid % GRID] = 0ull;
    const size_t n4 = (size_t)S * S / 4;
    const size_t stride = (size_t)gridDim.x * blockDim.x;
    for (size_t i = gtid; i < n4; i += stride) {
        float4 v = reinterpret_cast<const float4*>(log_trans)[i];
        __nv_bfloat162 lo, hi;
        lo.x = __float2bfloat16(__expf(v.x));
        lo.y = __float2bfloat16(__expf(v.y));
        hi.x = __float2bfloat16(__expf(v.z));
        hi.y = __float2bfloat16(__expf(v.w));
        reinterpret_cast<__nv_bfloat162*>(g_M)[2 * i]     = lo;
        reinterpret_cast<__nv_bfloat162*>(g_M)[2 * i + 1] = hi;
    }
}

// ---------------- helpers ----------------
__device__ __forceinline__ float warp_sum(float v) {
#pragma unroll
    for (int o = 16; o; o >>= 1) v += __shfl_xor_sync(0xffffffffu, v, o);
    return v;
}

// EXACT bf16 pair -> f32x2
__device__ __forceinline__ unsigned long long cvt2(unsigned u) {
    unsigned long long r;
    asm("mov.b64 %0, {%1, %2};" : "=l"(r) : "r"(u << 16), "r"(u & 0xffff0000u));
    return r;
}

__device__ __forceinline__ unsigned long long fma2(unsigned long long a,
                                                   unsigned long long b,
                                                   unsigned long long c) {
    unsigned long long d;
    asm("fma.rn.f32x2 %0, %1, %2, %3;" : "=l"(d) : "l"(a), "l"(b), "l"(c));
    return d;
}

__device__ __forceinline__ float f32x2_hsum(unsigned long long v) {
    unsigned lo, hi;
    asm("mov.b64 {%0, %1}, %2;" : "=r"(lo), "=r"(hi) : "l"(v));
    return __uint_as_float(lo) + __uint_as_float(hi);
}

__device__ __forceinline__ unsigned long long ldacq(const unsigned long long* p) {
    unsigned long long v;
    asm volatile("ld.acquire.gpu.global.b64 %0, [%1];" : "=l"(v) : "l"(p) : "memory");
    return v;
}
__device__ __forceinline__ void strel(unsigned long long* p, unsigned long long v) {
    asm volatile("st.release.gpu.global.b64 [%0], %1;" :: "l"(p), "l"(v) : "memory");
}
__device__ __forceinline__ void strelax(float* p, float v) {
    asm volatile("st.relaxed.gpu.global.f32 [%0], %1;" :: "l"(p), "f"(v) : "memory");
}

// Barrier + Z-reduce: WARP 0 ONLY, short post-publish window (R4-proven;
// no nanosleep — R8 showed no benefit). Ping-pong slots make exact-match
// spin deadlock-free (slot of gen rewritten only at gen+2).
__device__ __forceinline__ float poll_all(unsigned gen, int lane) {
    const unsigned long long* base = g_flag[gen & 1];
    unsigned long long x0, x1, x2, x3;
    for (;;) {
        x0 = ldacq(base + lane);
        x1 = ldacq(base + lane + 32);
        x2 = ldacq(base + lane + 64);
        x3 = ldacq(base + lane + 96);
        if (((unsigned)x0 == gen) & ((unsigned)x1 == gen) &
            ((unsigned)x2 == gen) & ((unsigned)x3 == gen)) break;
    }
    float z = __uint_as_float((unsigned)(x0 >> 32)) +
              __uint_as_float((unsigned)(x1 >> 32)) +
              __uint_as_float((unsigned)(x2 >> 32)) +
              __uint_as_float((unsigned)(x3 >> 32));
    return warp_sum(z);
}

// ---------------- persistent forward-filter kernel ----------------
__global__ void __launch_bounds__(BLOCK, 1) hmm_main_kernel(
    const float* __restrict__ log_M0,
    const float* __restrict__ log_emit,
    const int*   __restrict__ Tptr,
    float*       __restrict__ out)
{
    __shared__ float sw[S];                       // staged w (linear space)
    __shared__ __align__(16) float s_red[RPB][4];

    const int tid  = threadIdx.x;
    const int lane = tid & 31;
    const int warp = tid >> 5;
    const int g    = warp >> 2;   // row group 0..3
    const int q    = warp & 3;    // K quarter 0..3
    const int bid  = blockIdx.x;
    const int T    = *Tptr;

    const int r0 = bid * RPB;
    const uint4* A = reinterpret_cast<const uint4*>(
        g_M + (size_t)(r0 + g * RPG) * S + q * KQ);
    const float* swq = sw + q * KQ;

    double lik = 0.0;
    float invZ = 0.f;

    // ---- t = 0 ----
    if (warp == 0) {
        int row = r0 + lane;
        float v = __expf(__ldcg(log_M0 + row) + __ldcg(log_emit + row));
        strelax(&g_w[0][row], v);
        float part = warp_sum(v);
        __syncwarp();
        if (lane == 0)
            strel(&g_flag[1][bid],
                  ((unsigned long long)__float_as_uint(part) << 32) | 1u);
        float Z = poll_all(1u, lane);
        invZ = 1.0f / Z;
        if (bid == 0 && tid == 0) lik += (double)logf(Z);
    }
    __syncthreads();   // others wait for warp 0's poll (w0 globally visible)

    for (int t = 1; t <= T; ++t) {
        const int cur = t & 1, prev = cur ^ 1;
        const unsigned gen = (unsigned)(t + 1);

        // --- prefetch streamed rows (6,7) at loop TOP: their ~260cyc L2
        // latency hides under the sw copy + barrier below, and they cannot
        // delay the flag store (R8's mistake). Addresses are t-invariant. ---
        uint4 pf[8];
#pragma unroll
        for (int c = 0; c < 4; ++c) {
            float4 t6 = __ldcg(reinterpret_cast<const float4*>(A) + 6 * ROWSTRIDE + c * 32 + lane);
            float4 t7 = __ldcg(reinterpret_cast<const float4*>(A) + 7 * ROWSTRIDE + c * 32 + lane);
            pf[c]     = *reinterpret_cast<uint4*>(&t6);
            pf[4 + c] = *reinterpret_cast<uint4*>(&t7);
        }

        // emit prefetch (warp 0 only; consumed in epilogue)
        float em = 0.f;
        if (warp == 0) em = __ldcg(log_emit + (size_t)t * S + r0 + lane);

        // broadcast w_{t-1} into smem (each warp copies its 1/16 slice)
        {
            int j = warp * 64 + lane;
            float4 a = __ldcg(reinterpret_cast<const float4*>(g_w[prev]) + j);
            reinterpret_cast<float4*>(sw)[j] = a;
            j += 32;
            float4 b = __ldcg(reinterpret_cast<const float4*>(g_w[prev]) + j);
            reinterpret_cast<float4*>(sw)[j] = b;
        }
        __syncthreads();

        // --- dot: rows 0..5 from L1-pinned M (192KB/SM resident), rows 6..7
        // from the prefetch registers. Every warp has identical latency
        // profile -> no straggler warp. ---
        unsigned long long acc[8] = {0ull, 0ull, 0ull, 0ull, 0ull, 0ull, 0ull, 0ull};
#pragma unroll
        for (int c = 0; c < 4; ++c) {
            const int kb = c * 32 + lane;
            const ulonglong2 w01 = *reinterpret_cast<const ulonglong2*>(swq + c * 256 + lane * 8);
            const ulonglong2 w23 = *reinterpret_cast<const ulonglong2*>(swq + c * 256 + lane * 8 + 4);
#pragma unroll
            for (int r = 0; r < 6; ++r) {
                uint4 a = A[r * ROWSTRIDE + kb];
                acc[r] = fma2(cvt2(a.x), w01.x, acc[r]);
                acc[r] = fma2(cvt2(a.y), w01.y, acc[r]);
                acc[r] = fma2(cvt2(a.z), w23.x, acc[r]);
                acc[r] = fma2(cvt2(a.w), w23.y, acc[r]);
            }
            {
                uint4 a = pf[c];
                acc[6] = fma2(cvt2(a.x), w01.x, acc[6]);
                acc[6] = fma2(cvt2(a.y), w01.y, acc[6]);
                acc[6] = fma2(cvt2(a.z), w23.x, acc[6]);
                acc[6] = fma2(cvt2(a.w), w23.y, acc[6]);
                uint4 b = pf[4 + c];
                acc[7] = fma2(cvt2(b.x), w01.x, acc[7]);
                acc[7] = fma2(cvt2(b.y), w01.y, acc[7]);
                acc[7] = fma2(cvt2(b.z), w23.x, acc[7]);
                acc[7] = fma2(cvt2(b.w), w23.y, acc[7]);
            }
        }

#pragma unroll
        for (int r = 0; r < 8; ++r) {
            float s = warp_sum(f32x2_hsum(acc[r]));
            if (lane == 0) s_red[g * RPG + r][q] = s;
        }
        __syncthreads();

        // epilogue + publish + barrier: warp 0 only; others park at bar.sync
        if (warp == 0) {
            float4 p = *reinterpret_cast<const float4*>(s_red[lane]);
            float dotv = (p.x + p.y) + (p.z + p.w);
            float v = dotv * __expf(em) * invZ;
            strelax(&g_w[cur][r0 + lane], v);
            float part = warp_sum(v);
            __syncwarp();
            if (lane == 0)
                strel(&g_flag[gen & 1][bid],
                      ((unsigned long long)__float_as_uint(part) << 32) | gen);
            float Z = poll_all(gen, lane);
            invZ = 1.0f / Z;
            if (bid == 0 && tid == 0) lik += (double)logf(Z);
        }
        __syncthreads();
    }

    if (bid == 0 && tid == 0) out[0] = (float)lik;
}

// ---------------- launch ----------------
extern "C" void kernel_launch(void* const* d_in, const int* in_sizes, int n_in,
                              void* d_out, int out_size) {
    const float* log_M0    = (const float*)d_in[0];
    const float* log_trans = (const float*)d_in[1];
    const float* log_emit  = (const float*)d_in[2];
    const int*   Tptr      = (const int*)d_in[3];
    float* out = (float*)d_out;

    hmm_prep_kernel<<<2048, 256>>>(log_trans);
    hmm_main_kernel<<<GRID, BLOCK>>>(log_M0, log_emit, Tptr, out);
}